// round 1
// baseline (speedup 1.0000x reference)
#include <cuda_runtime.h>
#include <math.h>

// Global accumulators (allocation-guard-safe scratch).
__device__ double       g_total;
__device__ unsigned int g_count;

__global__ void init_kernel() {
    g_total = 0.0;
    g_count = 0u;
}

// One warp per triplet. D = 512 floats = 128 float4 per row; each lane
// loads float4 at positions lane + {0,32,64,96} from each of the 3 rows
// (12 coalesced LDG.128 per lane, MLP ~12).
__global__ __launch_bounds__(256) void triplet_kernel(
    const float* __restrict__ emb,       // [8192, 512]
    const int*   __restrict__ classes,   // [8192]
    const int*   __restrict__ triplets,  // [T, 3]
    const float* __restrict__ beta,      // [1000]
    int T)
{
    const int warp_in_blk = threadIdx.x >> 5;   // 0..7
    const int lane        = threadIdx.x & 31;
    const int t = blockIdx.x * 8 + warp_in_blk;

    __shared__ float s_tot[8];
    __shared__ int   s_cnt[8];

    float loss_w = 0.0f;
    int   cnt_w  = 0;

    if (t < T) {
        const int ai = triplets[3 * t + 0];
        const int pi = triplets[3 * t + 1];
        const int ni = triplets[3 * t + 2];

        const float4* __restrict__ A = (const float4*)emb + (size_t)ai * 128 + lane;
        const float4* __restrict__ P = (const float4*)emb + (size_t)pi * 128 + lane;
        const float4* __restrict__ N = (const float4*)emb + (size_t)ni * 128 + lane;

        float s_ap = 0.0f, s_an = 0.0f;
        #pragma unroll
        for (int k = 0; k < 4; k++) {
            const float4 a = A[k * 32];
            const float4 p = P[k * 32];
            const float4 n = N[k * 32];
            float d;
            d = a.x - p.x; s_ap = fmaf(d, d, s_ap);
            d = a.y - p.y; s_ap = fmaf(d, d, s_ap);
            d = a.z - p.z; s_ap = fmaf(d, d, s_ap);
            d = a.w - p.w; s_ap = fmaf(d, d, s_ap);
            d = a.x - n.x; s_an = fmaf(d, d, s_an);
            d = a.y - n.y; s_an = fmaf(d, d, s_an);
            d = a.z - n.z; s_an = fmaf(d, d, s_an);
            d = a.w - n.w; s_an = fmaf(d, d, s_an);
        }

        // warp reduction
        #pragma unroll
        for (int off = 16; off > 0; off >>= 1) {
            s_ap += __shfl_xor_sync(0xFFFFFFFFu, s_ap, off);
            s_an += __shfl_xor_sync(0xFFFFFFFFu, s_an, off);
        }

        if (lane == 0) {
            const float b    = beta[classes[ai]];
            const float d_ap = sqrtf(s_ap + 1e-8f);
            const float d_an = sqrtf(s_an + 1e-8f);
            const float pos  = fmaxf(d_ap - b + 0.2f, 0.0f);
            const float neg  = fmaxf(b - d_an + 0.2f, 0.0f);
            loss_w = pos + neg;
            cnt_w  = (pos > 0.0f || neg > 0.0f) ? 1 : 0;
        }
    }

    if (lane == 0) {
        s_tot[warp_in_blk] = loss_w;
        s_cnt[warp_in_blk] = cnt_w;
    }
    __syncthreads();

    if (threadIdx.x == 0) {
        float tt = 0.0f;
        int   cc = 0;
        #pragma unroll
        for (int i = 0; i < 8; i++) { tt += s_tot[i]; cc += s_cnt[i]; }
        atomicAdd(&g_total, (double)tt);
        atomicAdd(&g_count, (unsigned int)cc);
    }
}

__global__ void finalize_kernel(float* __restrict__ out) {
    const double       total = g_total;
    const unsigned int c     = g_count;
    float loss;
    if (c == 0u) {
        loss = (float)total;   // matches jnp.where(pair_count==0, total, ...)
    } else {
        loss = (float)(total / (double)c);
    }
    out[0] = loss;
}

extern "C" void kernel_launch(void* const* d_in, const int* in_sizes, int n_in,
                              void* d_out, int out_size) {
    const float* emb      = (const float*)d_in[0];   // [8192, 512] fp32
    const int*   classes  = (const int*)d_in[1];     // [8192] int32
    const int*   triplets = (const int*)d_in[2];     // [T, 3] int32
    const float* beta     = (const float*)d_in[3];   // [1000] fp32
    float*       out      = (float*)d_out;

    const int T = in_sizes[2] / 3;

    init_kernel<<<1, 1>>>();
    const int blocks = (T + 7) / 8;                  // 8 warps (triplets) per block
    triplet_kernel<<<blocks, 256>>>(emb, classes, triplets, beta, T);
    finalize_kernel<<<1, 1>>>(out);
}